// round 12
// baseline (speedup 1.0000x reference)
#include <cuda_runtime.h>
#include <cuda_fp16.h>
#include <cstdint>

// Problem dims (fixed)
#define N_IMG   8
#define C_IN    2048
#define HW      4096
#define C_OUT   512
#define M_TOTAL (N_IMG * HW)      // 32768

// GEMM tiling: CTA 128(m) x 256(n) x BK=128, 256 threads = 8 warps (2m x 4n),
// warp tile 64x64. 2 stages of (A 32KB + B 64KB) = 192KB smem, 1 CTA/SM.
#define BM 128
#define BN 256
#define BK 128
#define KT (C_IN / BK)            // 16
#define A_STAGE_BYTES 32768       // 128 k-rows x 256B (128 halfs of m)
#define B_STAGE_BYTES 65536       // 256 n-rows x 256B (128 halfs of k)
#define STAGE_BYTES   98304
#define SMEM_DYN (2 * STAGE_BYTES)   // 196608

// Weight center taps as fp16, [o][c]
__device__ __half g_B[C_OUT * C_IN];

// ---------------- pre-pass ----------------
__global__ void extract_w_kernel(const float* __restrict__ W) {
    int i4 = (blockIdx.x * 256 + threadIdx.x) * 4;
    __half h[4];
#pragma unroll
    for (int i = 0; i < 4; i++)
        h[i] = __float2half(W[(size_t)(i4 + i) * 9 + 4]);
    *reinterpret_cast<uint2*>(&g_B[i4]) = *reinterpret_cast<uint2*>(h);
}

// ---------------- helpers ----------------
__device__ __forceinline__ uint32_t smem_u32(const void* p) {
    uint32_t a;
    asm("{ .reg .u64 t; cvta.to.shared.u64 t, %1; cvt.u32.u64 %0, t; }" : "=r"(a) : "l"(p));
    return a;
}
__device__ __forceinline__ void cp16(uint32_t s, const void* g) {
    asm volatile("cp.async.cg.shared.global [%0], [%1], 16;" :: "r"(s), "l"(g));
}
#define CP_COMMIT() asm volatile("cp.async.commit_group;" ::: "memory")
#define CP_WAIT0()  asm volatile("cp.async.wait_group 0;" ::: "memory")

__device__ __forceinline__ void sts128(uint32_t addr, uint32_t r0, uint32_t r1,
                                       uint32_t r2, uint32_t r3) {
    asm volatile("st.shared.v4.b32 [%0], {%1,%2,%3,%4};"
                 :: "r"(addr), "r"(r0), "r"(r1), "r"(r2), "r"(r3) : "memory");
}
__device__ __forceinline__ void ldsm_x4(uint32_t& r0, uint32_t& r1, uint32_t& r2, uint32_t& r3,
                                        uint32_t addr) {
    asm volatile("ldmatrix.sync.aligned.m8n8.x4.shared.b16 {%0,%1,%2,%3}, [%4];"
                 : "=r"(r0), "=r"(r1), "=r"(r2), "=r"(r3) : "r"(addr));
}
__device__ __forceinline__ void ldsm_x4_t(uint32_t& r0, uint32_t& r1, uint32_t& r2, uint32_t& r3,
                                          uint32_t addr) {
    asm volatile("ldmatrix.sync.aligned.m8n8.x4.trans.shared.b16 {%0,%1,%2,%3}, [%4];"
                 : "=r"(r0), "=r"(r1), "=r"(r2), "=r"(r3) : "r"(addr));
}
__device__ __forceinline__ void mma16816(float* c, const uint32_t* a, const uint32_t* b) {
    asm volatile(
        "mma.sync.aligned.m16n8k16.row.col.f32.f16.f16.f32 "
        "{%0,%1,%2,%3}, {%4,%5,%6,%7}, {%8,%9}, {%0,%1,%2,%3};"
        : "+f"(c[0]), "+f"(c[1]), "+f"(c[2]), "+f"(c[3])
        : "r"(a[0]), "r"(a[1]), "r"(a[2]), "r"(a[3]), "r"(b[0]), "r"(b[1]));
}
__device__ __forceinline__ void cvt_sts(uint32_t addr, const float4& v0, const float4& v1) {
    __half2 h0 = __floats2half2_rn(v0.x, v0.y);
    __half2 h1 = __floats2half2_rn(v0.z, v0.w);
    __half2 h2 = __floats2half2_rn(v1.x, v1.y);
    __half2 h3 = __floats2half2_rn(v1.z, v1.w);
    sts128(addr, *reinterpret_cast<uint32_t*>(&h0), *reinterpret_cast<uint32_t*>(&h1),
                 *reinterpret_cast<uint32_t*>(&h2), *reinterpret_cast<uint32_t*>(&h3));
}

// ---------------- GEMM ----------------
__global__ void __launch_bounds__(256, 1)
gemm_kernel(const float* __restrict__ fea, const float* __restrict__ bias,
            float* __restrict__ out) {
    extern __shared__ char smem[];
    const uint32_t sb = smem_u32(smem);

    const int tid  = threadIdx.x;
    const int lane = tid & 31;
    const int wid  = tid >> 5;
    const int wm   = wid & 1;           // m-warp: offset wm*64
    const int wn   = wid >> 1;          // n-warp: offset wn*64 (0..3)
    const int ntile = blockIdx.x;       // 0..1
    const int mtile = blockIdx.y;       // 0..255

    const int m0   = mtile * BM;
    const int nimg = m0 >> 12;
    const int p0   = m0 & (HW - 1);

    // ---- A fp32 load mapping: 4 threads per k-row, 64 rows per batch ----
    // row r = (tid>>2) + 64*half ; per dj(0..3): dest chunk hc = (dj&1)+((dj>>1)<<3)+(tid&3)*2
    const int ar = tid >> 2;            // 0..63
    const int al = tid & 3;
    int hcv[4];
    uint32_t aStsOff[4];
#pragma unroll
    for (int dj = 0; dj < 4; dj++) {
        hcv[dj] = (dj & 1) + ((dj >> 1) << 3) + al * 2;
        aStsOff[dj] = (uint32_t)(ar * 256 + ((hcv[dj] ^ (ar & 7)) << 4));
    }
    const float* aRow = fea + (size_t)nimg * C_IN * HW + (size_t)ar * HW + p0;

    // ---- B cp.async mapping: one 256B row per thread, 16 chunks ----
    const __half* bRow = g_B + (size_t)(ntile * BN + tid) * C_IN;
    const uint32_t bSts0 = (uint32_t)(A_STAGE_BYTES + tid * 256);
    const int bxor = (tid & 7) << 4;

    // ---- ldmatrix lane addressing ----
    const int grp = lane >> 3, lr8 = lane & 7;
    const int krl   = (grp >> 1) * 8 + lr8;           // k row local within 16-block
    const int ac16b = wm * 8 + (grp & 1);             // A m-chunk base
    const int nrl   = (grp >> 1) * 8 + lr8;
    uint32_t aOff[4];
#pragma unroll
    for (int mb = 0; mb < 4; mb++)
        aOff[mb] = (uint32_t)(krl * 256 + (((ac16b + 2 * mb) ^ (krl & 7)) << 4));

    float acc[4][8][4];
#pragma unroll
    for (int i = 0; i < 4; i++)
#pragma unroll
        for (int j = 0; j < 8; j++)
#pragma unroll
            for (int q = 0; q < 4; q++) acc[i][j][q] = 0.f;

    // ---- prologue: fill stage 0 ----
    {
        const uint32_t st = sb;
#pragma unroll
        for (int half = 0; half < 2; half++) {
            const float* ap = aRow + (size_t)half * 64 * HW;
            float4 v0[4], v1[4];
#pragma unroll
            for (int dj = 0; dj < 4; dj++) {
                v0[dj] = *reinterpret_cast<const float4*>(ap + hcv[dj] * 8);
                v1[dj] = *reinterpret_cast<const float4*>(ap + hcv[dj] * 8 + 4);
            }
#pragma unroll
            for (int dj = 0; dj < 4; dj++)
                cvt_sts(st + aStsOff[dj] + half * 16384, v0[dj], v1[dj]);
        }
#pragma unroll
        for (int j = 0; j < 16; j++)
            cp16(st + bSts0 + ((j << 4) ^ bxor), bRow + j * 8);
        CP_COMMIT();
    }

    for (int kt = 0; kt < KT; kt++) {
        CP_WAIT0();
        __syncthreads();

        const bool pf = (kt + 1 < KT);
        const uint32_t stN  = sb + ((kt + 1) & 1) * STAGE_BYTES;  // produce
        const uint32_t base = sb + (kt & 1) * STAGE_BYTES;        // consume

        // A batch0 LDGs (k-rows 0..63 of tile kt+1) — issue before compute
        float4 v0[4], v1[4];
        const float* apN = aRow + (size_t)(kt + 1) * BK * HW;
        if (pf) {
#pragma unroll
            for (int dj = 0; dj < 4; dj++) {
                v0[dj] = *reinterpret_cast<const float4*>(apN + hcv[dj] * 8);
                v1[dj] = *reinterpret_cast<const float4*>(apN + hcv[dj] * 8 + 4);
            }
            // B for tile kt+1 (async, no regs)
            const __half* bp = bRow + (kt + 1) * BK;
#pragma unroll
            for (int j = 0; j < 16; j++)
                cp16(stN + bSts0 + ((j << 4) ^ bxor), bp + j * 8);
            CP_COMMIT();
        }

        // ---- compute ks 0..3 ----
#pragma unroll
        for (int ks = 0; ks < 4; ks++) {
            uint32_t aF[4][4], bF[8][2];
#pragma unroll
            for (int mb = 0; mb < 4; mb++)
                ldsm_x4_t(aF[mb][0], aF[mb][1], aF[mb][2], aF[mb][3],
                          base + aOff[mb] + (uint32_t)(ks * 4096));
#pragma unroll
            for (int nbp = 0; nbp < 4; nbp++) {
                const int nrow = wn * 64 + nbp * 16 + nrl;
                const uint32_t ba = base + (uint32_t)(A_STAGE_BYTES + nrow * 256
                                   + (((ks * 2 + (grp & 1)) ^ (nrow & 7)) << 4));
                ldsm_x4(bF[2 * nbp][0], bF[2 * nbp][1],
                        bF[2 * nbp + 1][0], bF[2 * nbp + 1][1], ba);
            }
#pragma unroll
            for (int mb = 0; mb < 4; mb++)
#pragma unroll
                for (int nb = 0; nb < 8; nb++)
                    mma16816(acc[mb][nb], aF[mb], bF[nb]);
        }

        // store batch0, issue batch1 LDGs (k-rows 64..127)
        if (pf) {
#pragma unroll
            for (int dj = 0; dj < 4; dj++)
                cvt_sts(stN + aStsOff[dj], v0[dj], v1[dj]);
            const float* ap1 = apN + (size_t)64 * HW;
#pragma unroll
            for (int dj = 0; dj < 4; dj++) {
                v0[dj] = *reinterpret_cast<const float4*>(ap1 + hcv[dj] * 8);
                v1[dj] = *reinterpret_cast<const float4*>(ap1 + hcv[dj] * 8 + 4);
            }
        }

        // ---- compute ks 4..7 ----
#pragma unroll
        for (int ks = 4; ks < 8; ks++) {
            uint32_t aF[4][4], bF[8][2];
#pragma unroll
            for (int mb = 0; mb < 4; mb++)
                ldsm_x4_t(aF[mb][0], aF[mb][1], aF[mb][2], aF[mb][3],
                          base + aOff[mb] + (uint32_t)(ks * 4096));
#pragma unroll
            for (int nbp = 0; nbp < 4; nbp++) {
                const int nrow = wn * 64 + nbp * 16 + nrl;
                const uint32_t ba = base + (uint32_t)(A_STAGE_BYTES + nrow * 256
                                   + (((ks * 2 + (grp & 1)) ^ (nrow & 7)) << 4));
                ldsm_x4(bF[2 * nbp][0], bF[2 * nbp][1],
                        bF[2 * nbp + 1][0], bF[2 * nbp + 1][1], ba);
            }
#pragma unroll
            for (int mb = 0; mb < 4; mb++)
#pragma unroll
                for (int nb = 0; nb < 8; nb++)
                    mma16816(acc[mb][nb], aF[mb], bF[nb]);
        }

        // store batch1
        if (pf) {
#pragma unroll
            for (int dj = 0; dj < 4; dj++)
                cvt_sts(stN + aStsOff[dj] + 16384, v0[dj], v1[dj]);
        }
    }

    // ---- epilogue: bias + relu, direct STG ----
    const int lr = lane >> 2;
    const int lc = (lane & 3) * 2;
    const int oBase = ntile * BN + wn * 64 + lc;
    const int pBase = p0 + wm * 64 + lr;
    float* outN = out + (size_t)nimg * C_OUT * HW;

#pragma unroll
    for (int nb = 0; nb < 8; nb++) {
        const int o = oBase + nb * 8;
        const float b0 = bias[o], b1 = bias[o + 1];
        float* r0p = outN + (size_t)o * HW;
        float* r1p = outN + (size_t)(o + 1) * HW;
#pragma unroll
        for (int mb = 0; mb < 4; mb++) {
            const int p = pBase + mb * 16;
            float v0f = acc[mb][nb][0] + b0;
            float v1f = acc[mb][nb][1] + b1;
            float v2f = acc[mb][nb][2] + b0;
            float v3f = acc[mb][nb][3] + b1;
            r0p[p]     = v0f > 0.f ? v0f : 0.f;
            r1p[p]     = v1f > 0.f ? v1f : 0.f;
            r0p[p + 8] = v2f > 0.f ? v2f : 0.f;
            r1p[p + 8] = v3f > 0.f ? v3f : 0.f;
        }
    }
}

// ---------------- launch ----------------
extern "C" void kernel_launch(void* const* d_in, const int* in_sizes, int n_in,
                              void* d_out, int out_size) {
    const float* fea = (const float*)d_in[0];
    const float* W   = (const float*)d_in[1];
    const float* b   = (const float*)d_in[2];
    float* out       = (float*)d_out;

    cudaFuncSetAttribute(gemm_kernel, cudaFuncAttributeMaxDynamicSharedMemorySize, SMEM_DYN);

    extract_w_kernel<<<(C_OUT * C_IN) / 1024, 256>>>(W);
    // ntile fastest so CTAs sharing an A m-tile co-run -> L2 dedup of fp32 A
    gemm_kernel<<<dim3(C_OUT / BN, M_TOTAL / BM), 256, SMEM_DYN>>>(fea, b, out);
}

// round 15
// speedup vs baseline: 1.4868x; 1.4868x over previous
#include <cuda_runtime.h>
#include <cuda_fp16.h>
#include <cstdint>

// Problem dims (fixed)
#define N_IMG   8
#define C_IN    2048
#define HW      4096
#define C_OUT   512
#define M_TOTAL (N_IMG * HW)      // 32768

// GEMM tiling: fat CTA 128(m) x 256(n), 256 threads = 8 warps (2m x 4n),
// warp tile 64x64, BK=64, 3 stages (proven R9 shape) + ks frag double-buffer
#define BM 128
#define BN 256
#define BK 64
#define KT (C_IN / BK)            // 32
#define STAGES 3
#define A_STAGE_BYTES 16384       // 64 k-rows x 256B
#define STAGE_BYTES   49152       // + 32KB B (256 n-rows x 128B)
#define SMEM_DYN (STAGES * STAGE_BYTES)   // 147456

// Weight center taps as fp16, [o][c]
__device__ __half g_B[C_OUT * C_IN];

// ---------------- pre-pass ----------------
__global__ void extract_w_kernel(const float* __restrict__ W) {
    int i4 = (blockIdx.x * 256 + threadIdx.x) * 4;
    __half h[4];
#pragma unroll
    for (int i = 0; i < 4; i++)
        h[i] = __float2half(W[(size_t)(i4 + i) * 9 + 4]);
    *reinterpret_cast<uint2*>(&g_B[i4]) = *reinterpret_cast<uint2*>(h);
}

// ---------------- helpers ----------------
__device__ __forceinline__ uint32_t smem_u32(const void* p) {
    uint32_t a;
    asm("{ .reg .u64 t; cvta.to.shared.u64 t, %1; cvt.u32.u64 %0, t; }" : "=r"(a) : "l"(p));
    return a;
}
__device__ __forceinline__ void cp16(uint32_t s, const void* g) {
    asm volatile("cp.async.cg.shared.global [%0], [%1], 16;" :: "r"(s), "l"(g));
}
#define CP_COMMIT() asm volatile("cp.async.commit_group;" ::: "memory")
#define CP_WAIT1()  asm volatile("cp.async.wait_group 1;" ::: "memory")
#define CP_WAIT0()  asm volatile("cp.async.wait_group 0;" ::: "memory")

__device__ __forceinline__ void sts128(uint32_t addr, uint32_t r0, uint32_t r1,
                                       uint32_t r2, uint32_t r3) {
    asm volatile("st.shared.v4.b32 [%0], {%1,%2,%3,%4};"
                 :: "r"(addr), "r"(r0), "r"(r1), "r"(r2), "r"(r3) : "memory");
}
__device__ __forceinline__ void ldsm_x4(uint32_t& r0, uint32_t& r1, uint32_t& r2, uint32_t& r3,
                                        uint32_t addr) {
    asm volatile("ldmatrix.sync.aligned.m8n8.x4.shared.b16 {%0,%1,%2,%3}, [%4];"
                 : "=r"(r0), "=r"(r1), "=r"(r2), "=r"(r3) : "r"(addr));
}
__device__ __forceinline__ void ldsm_x4_t(uint32_t& r0, uint32_t& r1, uint32_t& r2, uint32_t& r3,
                                          uint32_t addr) {
    asm volatile("ldmatrix.sync.aligned.m8n8.x4.trans.shared.b16 {%0,%1,%2,%3}, [%4];"
                 : "=r"(r0), "=r"(r1), "=r"(r2), "=r"(r3) : "r"(addr));
}
__device__ __forceinline__ void mma16816(float* c, const uint32_t* a, const uint32_t* b) {
    asm volatile(
        "mma.sync.aligned.m16n8k16.row.col.f32.f16.f16.f32 "
        "{%0,%1,%2,%3}, {%4,%5,%6,%7}, {%8,%9}, {%0,%1,%2,%3};"
        : "+f"(c[0]), "+f"(c[1]), "+f"(c[2]), "+f"(c[3])
        : "r"(a[0]), "r"(a[1]), "r"(a[2]), "r"(a[3]), "r"(b[0]), "r"(b[1]));
}
__device__ __forceinline__ void cvt_sts(uint32_t addr, const float4& v0, const float4& v1) {
    __half2 h0 = __floats2half2_rn(v0.x, v0.y);
    __half2 h1 = __floats2half2_rn(v0.z, v0.w);
    __half2 h2 = __floats2half2_rn(v1.x, v1.y);
    __half2 h3 = __floats2half2_rn(v1.z, v1.w);
    sts128(addr, *reinterpret_cast<uint32_t*>(&h0), *reinterpret_cast<uint32_t*>(&h1),
                 *reinterpret_cast<uint32_t*>(&h2), *reinterpret_cast<uint32_t*>(&h3));
}

// ---------------- GEMM ----------------
__global__ void __launch_bounds__(256, 1)
gemm_kernel(const float* __restrict__ fea, const float* __restrict__ bias,
            float* __restrict__ out) {
    extern __shared__ char smem[];
    const uint32_t sb = smem_u32(smem);

    const int tid  = threadIdx.x;
    const int lane = tid & 31;
    const int wid  = tid >> 5;
    const int wm   = wid & 1;           // m-warp: offset wm*64
    const int wn   = wid >> 1;          // n-warp: offset wn*64 (0..3)
    const int ntile = blockIdx.x;       // 0..1
    const int mtile = blockIdx.y;       // 0..255

    const int m0   = mtile * BM;
    const int nimg = m0 >> 12;
    const int p0   = m0 & (HW - 1);

    // ---- A global-load addressing: 32KB fp32 tile over 256 threads ----
    const int arow0 = tid >> 4;         // 0..15, +16 per j (j=0..3)
    const int ahc   = tid & 15;
    const float* aSrc = fea + (size_t)nimg * C_IN * HW + (size_t)arow0 * HW + p0 + ahc * 8;
    const uint32_t aSts0 = (uint32_t)(arow0 * 256 + ((ahc ^ (arow0 & 7)) << 4)); // +j*4096

    // ---- B cp.async addressing ----
    const int brow0 = tid >> 3;         // 0..31, +32 per j (j=0..7)
    const int bhc   = tid & 7;
    const __half* bSrc = g_B + (size_t)(ntile * BN + brow0) * C_IN + bhc * 8;
    const uint32_t bSts0 = (uint32_t)(A_STAGE_BYTES + brow0 * 128
                                      + ((bhc ^ (brow0 & 7)) << 4));             // +j*4096

    // ---- ldmatrix lane addressing ----
    const int grp = lane >> 3, lr8 = lane & 7;
    const int krl   = (grp >> 1) * 8 + lr8;
    const int ac16b = wm * 8 + (grp & 1);
    const int nrl   = (grp >> 1) * 8 + lr8;
    uint32_t aOff[4];
#pragma unroll
    for (int mb = 0; mb < 4; mb++)
        aOff[mb] = (uint32_t)(krl * 256 + (((ac16b + 2 * mb) ^ (krl & 7)) << 4));
    uint32_t bOffK[2];   // per (ks&1): chunk index (ks*2+(grp&1)) pattern; ks stride 32B
#pragma unroll
    for (int i = 0; i < 2; i++) bOffK[i] = 0; // placeholder (computed inline)

    float acc[4][8][4];
#pragma unroll
    for (int i = 0; i < 4; i++)
#pragma unroll
        for (int j = 0; j < 8; j++)
#pragma unroll
            for (int q = 0; q < 4; q++) acc[i][j][q] = 0.f;

    // ---- prologue: stages 0,1 ----
#pragma unroll
    for (int s = 0; s < 2; s++) {
        const uint32_t st = sb + s * STAGE_BYTES;
        const float* ap = aSrc + (size_t)s * BK * HW;
#pragma unroll
        for (int j = 0; j < 4; j++) {
            float4 v0 = *reinterpret_cast<const float4*>(ap + (size_t)j * 16 * HW);
            float4 v1 = *reinterpret_cast<const float4*>(ap + (size_t)j * 16 * HW + 4);
            cvt_sts(st + aSts0 + j * 4096, v0, v1);
        }
#pragma unroll
        for (int j = 0; j < 8; j++)
            cp16(st + bSts0 + j * 4096, bSrc + s * BK + (size_t)j * 32 * C_IN);
        CP_COMMIT();
    }

    uint32_t aF[2][4][4], bF[2][8][2];

    for (int kt = 0; kt < KT; kt++) {
        if (kt < KT - 1) { CP_WAIT1(); } else { CP_WAIT0(); }
        __syncthreads();

        const bool pf = (kt + 2 < KT);
        const uint32_t st = sb + ((kt + 2) % STAGES) * STAGE_BYTES;
        const uint32_t base = sb + (kt % STAGES) * STAGE_BYTES;

        // B prefetch for kt+2 (async)
        if (pf) {
#pragma unroll
            for (int j = 0; j < 8; j++)
                cp16(st + bSts0 + j * 4096, bSrc + (kt + 2) * BK + (size_t)j * 32 * C_IN);
            CP_COMMIT();
        }

        // A fp32 LDGs for kt+2: issue now, consume after compute (R6 schedule)
        float4 v0[4], v1[4];
        if (pf) {
            const float* ap = aSrc + (size_t)(kt + 2) * BK * HW;
#pragma unroll
            for (int j = 0; j < 4; j++) {
                v0[j] = *reinterpret_cast<const float4*>(ap + (size_t)j * 16 * HW);
                v1[j] = *reinterpret_cast<const float4*>(ap + (size_t)j * 16 * HW + 4);
            }
        }

        // ---- preload frags for ks=0 into buffer 0 ----
#pragma unroll
        for (int mb = 0; mb < 4; mb++)
            ldsm_x4_t(aF[0][mb][0], aF[0][mb][1], aF[0][mb][2], aF[0][mb][3],
                      base + aOff[mb]);
#pragma unroll
        for (int nbp = 0; nbp < 4; nbp++) {
            const int nrow = wn * 64 + nbp * 16 + nrl;
            ldsm_x4(bF[0][2 * nbp][0], bF[0][2 * nbp][1],
                    bF[0][2 * nbp + 1][0], bF[0][2 * nbp + 1][1],
                    base + (uint32_t)(A_STAGE_BYTES + nrow * 128
                                      + (((grp & 1) ^ (nrow & 7)) << 4)));
        }

        // ---- compute with ks-level double buffering ----
#pragma unroll
        for (int ks = 0; ks < 4; ks++) {
            const int cur = ks & 1, nxt = cur ^ 1;
            if (ks < 3) {
                const int kn = ks + 1;
#pragma unroll
                for (int mb = 0; mb < 4; mb++)
                    ldsm_x4_t(aF[nxt][mb][0], aF[nxt][mb][1], aF[nxt][mb][2], aF[nxt][mb][3],
                              base + aOff[mb] + (uint32_t)(kn * 4096));
#pragma unroll
                for (int nbp = 0; nbp < 4; nbp++) {
                    const int nrow = wn * 64 + nbp * 16 + nrl;
                    ldsm_x4(bF[nxt][2 * nbp][0], bF[nxt][2 * nbp][1],
                            bF[nxt][2 * nbp + 1][0], bF[nxt][2 * nbp + 1][1],
                            base + (uint32_t)(A_STAGE_BYTES + nrow * 128
                                   + (((kn * 2 + (grp & 1)) ^ (nrow & 7)) << 4)));
                }
            }
#pragma unroll
            for (int mb = 0; mb < 4; mb++)
#pragma unroll
                for (int nb = 0; nb < 8; nb++)
                    mma16816(acc[mb][nb], aF[cur][mb], bF[cur][nb]);
        }

        // ---- store A tile kt+2 ----
        if (pf) {
#pragma unroll
            for (int j = 0; j < 4; j++)
                cvt_sts(st + aSts0 + j * 4096, v0[j], v1[j]);
        }
    }

    // ---- epilogue: bias + relu, direct STG ----
    const int lr = lane >> 2;
    const int lc = (lane & 3) * 2;
    const int oBase = ntile * BN + wn * 64 + lc;
    const int pBase = p0 + wm * 64 + lr;
    float* outN = out + (size_t)nimg * C_OUT * HW;

#pragma unroll
    for (int nb = 0; nb < 8; nb++) {
        const int o = oBase + nb * 8;
        const float b0 = bias[o], b1 = bias[o + 1];
        float* r0p = outN + (size_t)o * HW;
        float* r1p = outN + (size_t)(o + 1) * HW;
#pragma unroll
        for (int mb = 0; mb < 4; mb++) {
            const int p = pBase + mb * 16;
            float v0f = acc[mb][nb][0] + b0;
            float v1f = acc[mb][nb][1] + b1;
            float v2f = acc[mb][nb][2] + b0;
            float v3f = acc[mb][nb][3] + b1;
            r0p[p]     = v0f > 0.f ? v0f : 0.f;
            r1p[p]     = v1f > 0.f ? v1f : 0.f;
            r0p[p + 8] = v2f > 0.f ? v2f : 0.f;
            r1p[p + 8] = v3f > 0.f ? v3f : 0.f;
        }
    }
}

// ---------------- launch ----------------
extern "C" void kernel_launch(void* const* d_in, const int* in_sizes, int n_in,
                              void* d_out, int out_size) {
    const float* fea = (const float*)d_in[0];
    const float* W   = (const float*)d_in[1];
    const float* b   = (const float*)d_in[2];
    float* out       = (float*)d_out;

    cudaFuncSetAttribute(gemm_kernel, cudaFuncAttributeMaxDynamicSharedMemorySize, SMEM_DYN);

    extract_w_kernel<<<(C_OUT * C_IN) / 1024, 256>>>(W);
    // ntile fastest so the 2 CTAs sharing an A m-tile co-run -> L2 dedup of fp32 A
    gemm_kernel<<<dim3(C_OUT / BN, M_TOTAL / BM), 256, SMEM_DYN>>>(fea, b, out);
}